// round 2
// baseline (speedup 1.0000x reference)
#include <cuda_runtime.h>
#include <math.h>

#define N_  256
#define T_  128
#define D_  512
#define H_  1024
#define C4_ 4096   // 4*H

// ---- device scratch (no runtime allocation allowed) ----
__device__ float g_G[N_ * T_ * C4_];   // precomputed x@Wx + b, gate-interleaved cols (512 MB)
__device__ float g_Wx_r[D_ * C4_];     // Wx, gate-interleaved columns
__device__ float g_W[2 * H_ * C4_];    // rows [0,H): Wh_r ; rows [H,2H): Wattn_r
__device__ float g_b[C4_];             // bias, gate-interleaved
__device__ float g_h[2][N_ * H_];      // ping-pong hidden state
__device__ float g_c[N_ * H_];         // cell state
__device__ float g_attn[N_ * H_];      // attention context per step

__device__ __forceinline__ float sigf(float x) { return 1.0f / (1.0f + expf(-x)); }

// Reorder weights so column c' = j*4 + q maps to original column q*H + j.
__global__ void reorder_kernel(const float* __restrict__ Wx, const float* __restrict__ Wh,
                               const float* __restrict__ Wattn, const float* __restrict__ b) {
    int stride = gridDim.x * blockDim.x;
    int tid0 = blockIdx.x * blockDim.x + threadIdx.x;
    for (int i = tid0; i < D_ * C4_; i += stride) {
        int c = i & (C4_ - 1);
        int oc = (c & 3) * H_ + (c >> 2);
        g_Wx_r[i] = Wx[(i >> 12) * C4_ + oc];
    }
    for (int i = tid0; i < H_ * C4_; i += stride) {
        int c = i & (C4_ - 1);
        int k = i >> 12;
        int oc = (c & 3) * H_ + (c >> 2);
        g_W[i]             = Wh[k * C4_ + oc];
        g_W[H_ * C4_ + i]  = Wattn[k * C4_ + oc];
    }
    for (int i = tid0; i < C4_; i += stride) {
        int oc = (i & 3) * H_ + (i >> 2);
        g_b[i] = b[oc];
    }
}

// h0 = c0 = mean over the 16 spatial locations of A[n][h][:]
__global__ void init_kernel(const float* __restrict__ A) {
    int i = blockIdx.x * blockDim.x + threadIdx.x;
    if (i < N_ * H_) {
        const float4* a = reinterpret_cast<const float4*>(A + (size_t)i * 16);
        float4 a0 = a[0], a1 = a[1], a2 = a[2], a3 = a[3];
        float s = a0.x + a0.y + a0.z + a0.w
                + a1.x + a1.y + a1.z + a1.w
                + a2.x + a2.y + a2.z + a2.w
                + a3.x + a3.y + a3.z + a3.w;
        s *= (1.0f / 16.0f);
        g_h[0][i] = s;
        g_c[i] = s;
    }
}

// G = x_2d (32768 x 512) @ g_Wx_r (512 x 4096) + g_b.  64x64 tiles, 4x4 per thread.
__global__ __launch_bounds__(256) void gemm_pre(const float* __restrict__ x) {
    __shared__ __align__(16) float As[16][64];   // As[k][m]
    __shared__ __align__(16) float Bs[16][64];   // Bs[k][c]
    int tid = threadIdx.x;
    int tx = tid & 15, ty = tid >> 4;
    int bm = blockIdx.y * 64;
    int bn = blockIdx.x * 64;
    float acc[4][4] = {};
    for (int k0 = 0; k0 < D_; k0 += 16) {
#pragma unroll
        for (int i = 0; i < 4; i++) {
            int lin = tid + i * 256;
            int m = lin >> 4, k = lin & 15;
            As[k][m] = x[(bm + m) * D_ + k0 + k];
            int kb = lin >> 6, cb = lin & 63;
            Bs[kb][cb] = g_Wx_r[(k0 + kb) * C4_ + bn + cb];
        }
        __syncthreads();
#pragma unroll
        for (int k = 0; k < 16; k++) {
            float4 a4 = *reinterpret_cast<const float4*>(&As[k][ty << 2]);
            float4 b4 = *reinterpret_cast<const float4*>(&Bs[k][tx << 2]);
            float ar[4] = {a4.x, a4.y, a4.z, a4.w};
            float br[4] = {b4.x, b4.y, b4.z, b4.w};
#pragma unroll
            for (int i2 = 0; i2 < 4; i2++)
#pragma unroll
                for (int j2 = 0; j2 < 4; j2++)
                    acc[i2][j2] += ar[i2] * br[j2];
        }
        __syncthreads();
    }
    float4 bb = *reinterpret_cast<const float4*>(&g_b[bn + (tx << 2)]);
#pragma unroll
    for (int i = 0; i < 4; i++) {
        int row = bm + (ty << 2) + i;
        float4 o;
        o.x = acc[i][0] + bb.x;
        o.y = acc[i][1] + bb.y;
        o.z = acc[i][2] + bb.z;
        o.w = acc[i][3] + bb.w;
        *reinterpret_cast<float4*>(&g_G[row * C4_ + bn + (tx << 2)]) = o;
    }
}

// Per-step attention: scores over L=16 locations, softmax, weighted sum.
__global__ __launch_bounds__(256) void attn_kernel(const float* __restrict__ A, int cur) {
    int n = blockIdx.x;
    int tid = threadIdx.x;
    const float* __restrict__ hn = g_h[cur] + n * H_;
    const float* __restrict__ An = A + (size_t)n * H_ * 16;
    float s[16];
#pragma unroll
    for (int l = 0; l < 16; l++) s[l] = 0.0f;
#pragma unroll
    for (int r = 0; r < 4; r++) {
        int hh = tid + r * 256;
        float hv = hn[hh];
        const float4* ar = reinterpret_cast<const float4*>(An + hh * 16);
#pragma unroll
        for (int v = 0; v < 4; v++) {
            float4 a = ar[v];
            s[v * 4 + 0] += a.x * hv;
            s[v * 4 + 1] += a.y * hv;
            s[v * 4 + 2] += a.z * hv;
            s[v * 4 + 3] += a.w * hv;
        }
    }
    __shared__ float red[256][17];
#pragma unroll
    for (int l = 0; l < 16; l++) red[tid][l] = s[l];
    __syncthreads();
    for (int st = 128; st > 0; st >>= 1) {
        if (tid < st) {
#pragma unroll
            for (int l = 0; l < 16; l++) red[tid][l] += red[tid + st][l];
        }
        __syncthreads();
    }
    // softmax (redundant in all threads; 16 values)
    float w[16];
    float mx = -1e30f;
#pragma unroll
    for (int l = 0; l < 16; l++) {
        w[l] = red[0][l] * 0.03125f;   // 1/sqrt(1024)
        mx = fmaxf(mx, w[l]);
    }
    float sum = 0.0f;
#pragma unroll
    for (int l = 0; l < 16; l++) { w[l] = expf(w[l] - mx); sum += w[l]; }
    float inv = 1.0f / sum;
#pragma unroll
    for (int l = 0; l < 16; l++) w[l] *= inv;
#pragma unroll
    for (int r = 0; r < 4; r++) {
        int hh = tid + r * 256;
        const float4* ar = reinterpret_cast<const float4*>(An + hh * 16);
        float acc = 0.0f;
#pragma unroll
        for (int v = 0; v < 4; v++) {
            float4 a = ar[v];
            acc += a.x * w[v * 4 + 0] + a.y * w[v * 4 + 1]
                 + a.z * w[v * 4 + 2] + a.w * w[v * 4 + 3];
        }
        g_attn[n * H_ + hh] = acc;
    }
}

// Per-step fused GEMM + LSTM pointwise.
// gates[n][c'] = G[n,t][c'] + sum_k [h|attn][n][k] * g_W[k][c'], then LSTM update.
__global__ __launch_bounds__(256) void step_kernel(int t, int cur, float* __restrict__ out) {
    __shared__ __align__(16) float As[16][64];
    __shared__ __align__(16) float Bs[16][64];
    int tid = threadIdx.x;
    int tx = tid & 15, ty = tid >> 4;
    int bm = blockIdx.y * 64;   // batch-row base
    int bn = blockIdx.x * 64;   // gate-interleaved column base
    const float* __restrict__ hcur = g_h[cur];
    float acc[4][4] = {};
    for (int k0 = 0; k0 < 2 * H_; k0 += 16) {
        const float* __restrict__ Z = (k0 < H_) ? hcur : g_attn;
        int kk = k0 & (H_ - 1);
#pragma unroll
        for (int i = 0; i < 4; i++) {
            int lin = tid + i * 256;
            int m = lin >> 4, k = lin & 15;
            As[k][m] = Z[(bm + m) * H_ + kk + k];
            int kb = lin >> 6, cb = lin & 63;
            Bs[kb][cb] = g_W[(k0 + kb) * C4_ + bn + cb];
        }
        __syncthreads();
#pragma unroll
        for (int k = 0; k < 16; k++) {
            float4 a4 = *reinterpret_cast<const float4*>(&As[k][ty << 2]);
            float4 b4 = *reinterpret_cast<const float4*>(&Bs[k][tx << 2]);
            float ar[4] = {a4.x, a4.y, a4.z, a4.w};
            float br[4] = {b4.x, b4.y, b4.z, b4.w};
#pragma unroll
            for (int i2 = 0; i2 < 4; i2++)
#pragma unroll
                for (int j2 = 0; j2 < 4; j2++)
                    acc[i2][j2] += ar[i2] * br[j2];
        }
        __syncthreads();
    }
    // epilogue: each thread owns 4 rows x one full (i,f,o,g) quadruple
    int j = (bn >> 2) + tx;
    int nxt = cur ^ 1;
#pragma unroll
    for (int i = 0; i < 4; i++) {
        int n = bm + (ty << 2) + i;
        float4 g4 = *reinterpret_cast<const float4*>(&g_G[(n * T_ + t) * C4_ + bn + (tx << 2)]);
        float gi = acc[i][0] + g4.x;
        float gf = acc[i][1] + g4.y;
        float go = acc[i][2] + g4.z;
        float gg = acc[i][3] + g4.w;
        float cold = g_c[n * H_ + j];
        float cn = sigf(gf) * cold + sigf(gi) * tanhf(gg);
        float hn = sigf(go) * tanhf(cn);
        g_c[n * H_ + j] = cn;
        g_h[nxt][n * H_ + j] = hn;
        out[(n * T_ + t) * H_ + j] = hn;
    }
}

extern "C" void kernel_launch(void* const* d_in, const int* in_sizes, int n_in,
                              void* d_out, int out_size) {
    (void)in_sizes; (void)n_in; (void)out_size;
    const float* x     = (const float*)d_in[0];
    const float* A     = (const float*)d_in[1];
    const float* Wx    = (const float*)d_in[2];
    const float* Wh    = (const float*)d_in[3];
    const float* Wattn = (const float*)d_in[4];
    const float* b     = (const float*)d_in[5];
    float* out = (float*)d_out;

    reorder_kernel<<<2048, 256>>>(Wx, Wh, Wattn, b);
    init_kernel<<<(N_ * H_ + 255) / 256, 256>>>(A);
    gemm_pre<<<dim3(C4_ / 64, (N_ * T_) / 64), 256>>>(x);

    int cur = 0;
    for (int t = 0; t < T_; t++) {
        attn_kernel<<<N_, 256>>>(A, cur);
        step_kernel<<<dim3(C4_ / 64, N_ / 64), 256>>>(t, cur, out);
        cur ^= 1;
    }
}

// round 3
// speedup vs baseline: 2.3420x; 2.3420x over previous
#include <cuda_runtime.h>
#include <cuda_bf16.h>
#include <math.h>

#define N_  256
#define T_  128
#define D_  512
#define H_  1024
#define C4_ 4096
#define KT_ 2560   // H (h) + H (attn) + D (x)

// ---- device scratch (no runtime allocation allowed) ----
__device__ __align__(16) unsigned int g_Wt[(size_t)C4_ * KT_]; // packed (bf16 hi | bf16 lo<<16), [col][k], 42MB
__device__ __align__(16) float        g_bv[C4_];               // gate-interleaved bias
__device__ __align__(16) float        g_h[2][N_ * H_];         // fp32 hidden (ping-pong)
__device__ __align__(16) unsigned int g_zh[2][N_ * H_];        // packed bf16 split of h (ping-pong)
__device__ __align__(16) unsigned int g_za[N_ * H_];           // packed bf16 split of attn
__device__ __align__(16) float        g_c[N_ * H_];            // cell state

__device__ __forceinline__ float sigf(float x) { return 1.0f / (1.0f + expf(-x)); }

__device__ __forceinline__ unsigned int pack_split(float v) {
    __nv_bfloat16 h = __float2bfloat16(v);
    float r = v - __bfloat162float(h);
    __nv_bfloat16 l = __float2bfloat16(r);
    return (unsigned int)__bfloat16_as_ushort(h) | ((unsigned int)__bfloat16_as_ushort(l) << 16);
}

__device__ __forceinline__ void mma_bf16(float c[4], const unsigned int a[4], const unsigned int b[2]) {
    asm volatile(
        "mma.sync.aligned.m16n8k16.row.col.f32.bf16.bf16.f32 "
        "{%0,%1,%2,%3},{%4,%5,%6,%7},{%8,%9},{%0,%1,%2,%3};"
        : "+f"(c[0]), "+f"(c[1]), "+f"(c[2]), "+f"(c[3])
        : "r"(a[0]), "r"(a[1]), "r"(a[2]), "r"(a[3]), "r"(b[0]), "r"(b[1]));
}

// Build g_Wt[c][k] packed: col c' = j*4+q <-> original col q*H+j. Rows k: [0,H)=Wh, [H,2H)=Wattn, [2H,2H+D)=Wx.
__global__ void reorder_kernel(const float* __restrict__ Wx, const float* __restrict__ Wh,
                               const float* __restrict__ Wattn, const float* __restrict__ b) {
    int k = blockIdx.x * blockDim.x + threadIdx.x;   // 0..2559
    int c = blockIdx.y;                              // 0..4095
    if (k >= KT_) return;
    int oc = (c & 3) * H_ + (c >> 2);
    float w;
    if (k < H_)            w = Wh[k * C4_ + oc];
    else if (k < 2 * H_)   w = Wattn[(k - H_) * C4_ + oc];
    else                   w = Wx[(k - 2 * H_) * C4_ + oc];
    g_Wt[(size_t)c * KT_ + k] = pack_split(w);
    if (k == 0 && blockIdx.x == 0) g_bv[c] = b[oc];
}

// h0 = c0 = mean over 16 spatial locations of A[n][h][:]
__global__ void init_kernel(const float* __restrict__ A) {
    int i = blockIdx.x * blockDim.x + threadIdx.x;
    if (i < N_ * H_) {
        const float4* a = reinterpret_cast<const float4*>(A + (size_t)i * 16);
        float4 a0 = a[0], a1 = a[1], a2 = a[2], a3 = a[3];
        float s = a0.x + a0.y + a0.z + a0.w + a1.x + a1.y + a1.z + a1.w
                + a2.x + a2.y + a2.z + a2.w + a3.x + a3.y + a3.z + a3.w;
        s *= (1.0f / 16.0f);
        g_h[0][i] = s;
        g_c[i] = s;
        g_zh[0][i] = pack_split(s);
    }
}

// Single-pass attention: A rows held in registers across the softmax.
__global__ __launch_bounds__(256) void attn_kernel(const float* __restrict__ A, int cur) {
    int n = blockIdx.x;
    int tid = threadIdx.x;
    const float* __restrict__ hn = g_h[cur] + n * H_;
    const float* __restrict__ An = A + (size_t)n * H_ * 16;

    float4 ar[4][4];
    float hv[4];
    float s[16];
#pragma unroll
    for (int l = 0; l < 16; l++) s[l] = 0.0f;
#pragma unroll
    for (int r = 0; r < 4; r++) {
        int hh = tid + r * 256;
        hv[r] = hn[hh];
        const float4* ap = reinterpret_cast<const float4*>(An + hh * 16);
#pragma unroll
        for (int v = 0; v < 4; v++) {
            float4 a = ap[v];
            ar[r][v] = a;
            s[v * 4 + 0] += a.x * hv[r];
            s[v * 4 + 1] += a.y * hv[r];
            s[v * 4 + 2] += a.z * hv[r];
            s[v * 4 + 3] += a.w * hv[r];
        }
    }
    // warp butterfly reduce (all lanes end with warp sum)
#pragma unroll
    for (int off = 16; off > 0; off >>= 1)
#pragma unroll
        for (int l = 0; l < 16; l++) s[l] += __shfl_xor_sync(0xffffffffu, s[l], off);

    __shared__ float red[8][16];
    int wid = tid >> 5, lane = tid & 31;
    if (lane == 0)
#pragma unroll
        for (int l = 0; l < 16; l++) red[wid][l] = s[l];
    __syncthreads();

    float w[16];
    float mx = -1e30f;
#pragma unroll
    for (int l = 0; l < 16; l++) {
        float t = 0.0f;
#pragma unroll
        for (int ww = 0; ww < 8; ww++) t += red[ww][l];
        w[l] = t * 0.03125f;   // 1/sqrt(1024)
        mx = fmaxf(mx, w[l]);
    }
    float sum = 0.0f;
#pragma unroll
    for (int l = 0; l < 16; l++) { w[l] = expf(w[l] - mx); sum += w[l]; }
    float inv = 1.0f / sum;
#pragma unroll
    for (int l = 0; l < 16; l++) w[l] *= inv;

#pragma unroll
    for (int r = 0; r < 4; r++) {
        int hh = tid + r * 256;
        float acc = 0.0f;
#pragma unroll
        for (int v = 0; v < 4; v++) {
            float4 a = ar[r][v];
            acc += a.x * w[v * 4 + 0] + a.y * w[v * 4 + 1]
                 + a.z * w[v * 4 + 2] + a.w * w[v * 4 + 3];
        }
        g_za[n * H_ + hh] = pack_split(acc);
    }
}

// ----------------- fused step: [h|attn|x_t] @ W  (bf16-split, mma.sync) + LSTM -----------------
#define KC 32
#define SA 40   // padded smem row stride (halves)
#define SB 40
#define CS 132  // Cs stride (floats)

__global__ __launch_bounds__(256) void step_kernel(const float* __restrict__ x,
                                                   float* __restrict__ out, int t, int cur) {
    __shared__ __align__(16) unsigned char smraw[64 * CS * 4]; // 33792 B, unioned
    unsigned short* A_hi = (unsigned short*)smraw;                  // [64][SA]
    unsigned short* A_lo = A_hi + 64 * SA;
    unsigned short* B_hi = A_lo + 64 * SA;                          // [128][SB]
    unsigned short* B_lo = B_hi + 128 * SB;
    float* Cs = (float*)smraw;

    const int tid = threadIdx.x;
    const int bn = blockIdx.x * 128;   // column base (gate-interleaved)
    const int bm = blockIdx.y * 64;    // batch-row base
    const int nxt = cur ^ 1;

    const int rowA = tid >> 2, kA = (tid & 3) * 8;   // A: 8 u32/thread
    const int colB = tid >> 1, kB = (tid & 1) * 16;  // B: 16 u32/thread

    const int wid = tid >> 5, lane = tid & 31;
    const int wm = wid >> 2, wn = wid & 3;           // 2 x 4 warp grid
    const int g = lane >> 2, tg = lane & 3;

    float acc[2][4][4];
#pragma unroll
    for (int mt = 0; mt < 2; mt++)
#pragma unroll
        for (int nt = 0; nt < 4; nt++)
#pragma unroll
            for (int q = 0; q < 4; q++) acc[mt][nt][q] = 0.0f;

    unsigned int pa[8];
    unsigned int pb[16];

    // ---- prefetch tile 0 ----
    {
        int nrow = bm + rowA;
        int gk = kA;  // k0 = 0 -> h segment
        const uint4* p = (const uint4*)&g_zh[cur][nrow * H_ + gk];
        uint4 v0 = p[0], v1 = p[1];
        pa[0] = v0.x; pa[1] = v0.y; pa[2] = v0.z; pa[3] = v0.w;
        pa[4] = v1.x; pa[5] = v1.y; pa[6] = v1.z; pa[7] = v1.w;
        const uint4* q = (const uint4*)&g_Wt[(size_t)(bn + colB) * KT_ + kB];
#pragma unroll
        for (int i = 0; i < 4; i++) {
            uint4 v = q[i];
            pb[i * 4 + 0] = v.x; pb[i * 4 + 1] = v.y; pb[i * 4 + 2] = v.z; pb[i * 4 + 3] = v.w;
        }
    }

    for (int tile = 0; tile < KT_ / KC; tile++) {
        __syncthreads();  // previous tile's mma done
        // ---- store prefetched regs -> smem (split hi/lo) ----
        {
            uint2 u;
            u.x = (pa[0] & 0xffffu) | ((pa[1] & 0xffffu) << 16);
            u.y = (pa[2] & 0xffffu) | ((pa[3] & 0xffffu) << 16);
            *(uint2*)&A_hi[rowA * SA + kA] = u;
            u.x = (pa[4] & 0xffffu) | ((pa[5] & 0xffffu) << 16);
            u.y = (pa[6] & 0xffffu) | ((pa[7] & 0xffffu) << 16);
            *(uint2*)&A_hi[rowA * SA + kA + 4] = u;
            u.x = (pa[0] >> 16) | (pa[1] & 0xffff0000u);
            u.y = (pa[2] >> 16) | (pa[3] & 0xffff0000u);
            *(uint2*)&A_lo[rowA * SA + kA] = u;
            u.x = (pa[4] >> 16) | (pa[5] & 0xffff0000u);
            u.y = (pa[6] >> 16) | (pa[7] & 0xffff0000u);
            *(uint2*)&A_lo[rowA * SA + kA + 4] = u;
#pragma unroll
            for (int i = 0; i < 4; i++) {
                uint2 uh, ul;
                uh.x = (pb[i*4+0] & 0xffffu) | ((pb[i*4+1] & 0xffffu) << 16);
                uh.y = (pb[i*4+2] & 0xffffu) | ((pb[i*4+3] & 0xffffu) << 16);
                ul.x = (pb[i*4+0] >> 16) | (pb[i*4+1] & 0xffff0000u);
                ul.y = (pb[i*4+2] >> 16) | (pb[i*4+3] & 0xffff0000u);
                *(uint2*)&B_hi[colB * SB + kB + 4 * i] = uh;
                *(uint2*)&B_lo[colB * SB + kB + 4 * i] = ul;
            }
        }
        __syncthreads();

        // ---- prefetch next tile (overlaps with mma) ----
        if (tile + 1 < KT_ / KC) {
            int k0 = (tile + 1) * KC;
            int nrow = bm + rowA;
            int gk = k0 + kA;
            if (gk < H_) {
                const uint4* p = (const uint4*)&g_zh[cur][nrow * H_ + gk];
                uint4 v0 = p[0], v1 = p[1];
                pa[0]=v0.x; pa[1]=v0.y; pa[2]=v0.z; pa[3]=v0.w;
                pa[4]=v1.x; pa[5]=v1.y; pa[6]=v1.z; pa[7]=v1.w;
            } else if (gk < 2 * H_) {
                const uint4* p = (const uint4*)&g_za[nrow * H_ + (gk - H_)];
                uint4 v0 = p[0], v1 = p[1];
                pa[0]=v0.x; pa[1]=v0.y; pa[2]=v0.z; pa[3]=v0.w;
                pa[4]=v1.x; pa[5]=v1.y; pa[6]=v1.z; pa[7]=v1.w;
            } else {
                const float4* p = (const float4*)&x[((size_t)nrow * T_ + t) * D_ + (gk - 2 * H_)];
                float4 f0 = p[0], f1 = p[1];
                pa[0] = pack_split(f0.x); pa[1] = pack_split(f0.y);
                pa[2] = pack_split(f0.z); pa[3] = pack_split(f0.w);
                pa[4] = pack_split(f1.x); pa[5] = pack_split(f1.y);
                pa[6] = pack_split(f1.z); pa[7] = pack_split(f1.w);
            }
            const uint4* q = (const uint4*)&g_Wt[(size_t)(bn + colB) * KT_ + k0 + kB];
#pragma unroll
            for (int i = 0; i < 4; i++) {
                uint4 v = q[i];
                pb[i*4+0] = v.x; pb[i*4+1] = v.y; pb[i*4+2] = v.z; pb[i*4+3] = v.w;
            }
        }

        // ---- mma over this smem tile ----
#pragma unroll
        for (int kb = 0; kb < KC; kb += 16) {
            unsigned int ah[2][4], al[2][4], bh[4][2], bl[4][2];
#pragma unroll
            for (int mt = 0; mt < 2; mt++) {
                int r0 = wm * 32 + mt * 16 + g;
                int r1 = r0 + 8;
                int kk = kb + tg * 2;
                ah[mt][0] = *(const unsigned int*)&A_hi[r0 * SA + kk];
                ah[mt][1] = *(const unsigned int*)&A_hi[r1 * SA + kk];
                ah[mt][2] = *(const unsigned int*)&A_hi[r0 * SA + kk + 8];
                ah[mt][3] = *(const unsigned int*)&A_hi[r1 * SA + kk + 8];
                al[mt][0] = *(const unsigned int*)&A_lo[r0 * SA + kk];
                al[mt][1] = *(const unsigned int*)&A_lo[r1 * SA + kk];
                al[mt][2] = *(const unsigned int*)&A_lo[r0 * SA + kk + 8];
                al[mt][3] = *(const unsigned int*)&A_lo[r1 * SA + kk + 8];
            }
#pragma unroll
            for (int nt = 0; nt < 4; nt++) {
                int col = wn * 32 + nt * 8 + g;
                int kk = kb + tg * 2;
                bh[nt][0] = *(const unsigned int*)&B_hi[col * SB + kk];
                bh[nt][1] = *(const unsigned int*)&B_hi[col * SB + kk + 8];
                bl[nt][0] = *(const unsigned int*)&B_lo[col * SB + kk];
                bl[nt][1] = *(const unsigned int*)&B_lo[col * SB + kk + 8];
            }
#pragma unroll
            for (int mt = 0; mt < 2; mt++)
#pragma unroll
                for (int nt = 0; nt < 4; nt++) {
                    mma_bf16(acc[mt][nt], ah[mt], bh[nt]);
                    mma_bf16(acc[mt][nt], ah[mt], bl[nt]);
                    mma_bf16(acc[mt][nt], al[mt], bh[nt]);
                }
        }
    }

    // ---- epilogue: regroup gates via smem, fused LSTM pointwise ----
    __syncthreads();
#pragma unroll
    for (int mt = 0; mt < 2; mt++)
#pragma unroll
        for (int nt = 0; nt < 4; nt++) {
            int r0 = wm * 32 + mt * 16 + g;
            int col = wn * 32 + nt * 8 + tg * 2;
            Cs[r0 * CS + col]       = acc[mt][nt][0];
            Cs[r0 * CS + col + 1]   = acc[mt][nt][1];
            Cs[(r0+8) * CS + col]   = acc[mt][nt][2];
            Cs[(r0+8) * CS + col+1] = acc[mt][nt][3];
        }
    __syncthreads();

#pragma unroll
    for (int i = 0; i < 8; i++) {
        int lin = tid + i * 256;
        int m = lin >> 5, jj = lin & 31;
        float4 gg = *(const float4*)&Cs[m * CS + jj * 4];
        float4 bb = *(const float4*)&g_bv[bn + jj * 4];
        int n = bm + m;
        int j = (bn >> 2) + jj;
        float gi = gg.x + bb.x;
        float gf = gg.y + bb.y;
        float go = gg.z + bb.z;
        float gq = gg.w + bb.w;
        float cold = g_c[n * H_ + j];
        float cn = sigf(gf) * cold + sigf(gi) * tanhf(gq);
        float hn = sigf(go) * tanhf(cn);
        g_c[n * H_ + j] = cn;
        g_h[nxt][n * H_ + j] = hn;
        g_zh[nxt][n * H_ + j] = pack_split(hn);
        out[((size_t)n * T_ + t) * H_ + j] = hn;
    }
}

extern "C" void kernel_launch(void* const* d_in, const int* in_sizes, int n_in,
                              void* d_out, int out_size) {
    (void)in_sizes; (void)n_in; (void)out_size;
    const float* x     = (const float*)d_in[0];
    const float* A     = (const float*)d_in[1];
    const float* Wx    = (const float*)d_in[2];
    const float* Wh    = (const float*)d_in[3];
    const float* Wattn = (const float*)d_in[4];
    const float* b     = (const float*)d_in[5];
    float* out = (float*)d_out;

    reorder_kernel<<<dim3(KT_ / 256, C4_), 256>>>(Wx, Wh, Wattn, b);
    init_kernel<<<(N_ * H_ + 255) / 256, 256>>>(A);

    int cur = 0;
    for (int t = 0; t < T_; t++) {
        attn_kernel<<<N_, 256>>>(A, cur);
        step_kernel<<<dim3(C4_ / 128, N_ / 64), 256>>>(x, out, t, cur);
        cur ^= 1;
    }
}

// round 6
// speedup vs baseline: 2.9265x; 1.2495x over previous
#include <cuda_runtime.h>
#include <cuda_bf16.h>
#include <math.h>

#define N_  256
#define T_  128
#define D_  512
#define H_  1024
#define C4_ 4096
#define KT_ 2560            // H (h) + H (attn) + D (x)
#define KC  32
#define NTILES (KT_/KC)     // 80
#define STAGES 4
#define SA 40               // smem row stride in halves (80B, conflict-free for ldmatrix)
#define SB 40
#define STAGE_BYTES (2*(64*SA*2) + 2*(128*SB*2))   // 30720 B per stage
#define CS 132              // epilogue Cs stride (floats)

// ---- device scratch (no runtime allocation allowed) ----
__device__ __align__(16) __nv_bfloat16 g_Wh[(size_t)C4_ * KT_]; // weight hi, [col][k]
__device__ __align__(16) __nv_bfloat16 g_Wl[(size_t)C4_ * KT_]; // weight lo
__device__ __align__(16) __nv_bfloat16 g_xh[(size_t)N_ * T_ * D_];
__device__ __align__(16) __nv_bfloat16 g_xl[(size_t)N_ * T_ * D_];
__device__ __align__(16) float         g_bv[C4_];
__device__ __align__(16) float         g_h[2][N_ * H_];
__device__ __align__(16) __nv_bfloat16 g_zh[2][N_ * H_];  // h hi (ping-pong)
__device__ __align__(16) __nv_bfloat16 g_zl[2][N_ * H_];  // h lo
__device__ __align__(16) __nv_bfloat16 g_ah[N_ * H_];     // attn hi
__device__ __align__(16) __nv_bfloat16 g_al[N_ * H_];     // attn lo
__device__ __align__(16) float         g_c[N_ * H_];

__device__ __forceinline__ float sigf(float x) { return 1.0f / (1.0f + expf(-x)); }

__device__ __forceinline__ void split2(float v, __nv_bfloat16& hi, __nv_bfloat16& lo) {
    hi = __float2bfloat16(v);
    lo = __float2bfloat16(v - __bfloat162float(hi));
}

__device__ __forceinline__ void mma_bf16(float c[4], const unsigned int a[4], const unsigned int b[2]) {
    asm volatile(
        "mma.sync.aligned.m16n8k16.row.col.f32.bf16.bf16.f32 "
        "{%0,%1,%2,%3},{%4,%5,%6,%7},{%8,%9},{%0,%1,%2,%3};"
        : "+f"(c[0]), "+f"(c[1]), "+f"(c[2]), "+f"(c[3])
        : "r"(a[0]), "r"(a[1]), "r"(a[2]), "r"(a[3]), "r"(b[0]), "r"(b[1]));
}

__device__ __forceinline__ void ldsm_x4(unsigned int a[4], unsigned int addr) {
    asm volatile("ldmatrix.sync.aligned.m8n8.x4.shared.b16 {%0,%1,%2,%3}, [%4];"
                 : "=r"(a[0]), "=r"(a[1]), "=r"(a[2]), "=r"(a[3]) : "r"(addr));
}
__device__ __forceinline__ void ldsm_x2(unsigned int b[2], unsigned int addr) {
    asm volatile("ldmatrix.sync.aligned.m8n8.x2.shared.b16 {%0,%1}, [%2];"
                 : "=r"(b[0]), "=r"(b[1]) : "r"(addr));
}
__device__ __forceinline__ void cpa16(unsigned int dst, const void* src) {
    asm volatile("cp.async.cg.shared.global [%0], [%1], 16;" :: "r"(dst), "l"(src));
}

// ---- one-time prep kernels ----
// g_Wh/g_Wl[c][k]: col c' = j*4+q <-> original col q*H+j; k rows: [0,H)=Wh, [H,2H)=Wattn, [2H,..)=Wx
__global__ void reorder_kernel(const float* __restrict__ Wx, const float* __restrict__ Wh,
                               const float* __restrict__ Wattn, const float* __restrict__ b) {
    int k = blockIdx.x * blockDim.x + threadIdx.x;
    int c = blockIdx.y;
    if (k >= KT_) return;
    int oc = (c & 3) * H_ + (c >> 2);
    float w;
    if (k < H_)            w = Wh[k * C4_ + oc];
    else if (k < 2 * H_)   w = Wattn[(k - H_) * C4_ + oc];
    else                   w = Wx[(k - 2 * H_) * C4_ + oc];
    __nv_bfloat16 hi, lo;
    split2(w, hi, lo);
    g_Wh[(size_t)c * KT_ + k] = hi;
    g_Wl[(size_t)c * KT_ + k] = lo;
    if (k == 0 && blockIdx.x == 0) g_bv[c] = b[oc];
}

__global__ void xsplit_kernel(const float* __restrict__ x) {
    size_t i = (size_t)blockIdx.x * blockDim.x + threadIdx.x;
    size_t total = (size_t)N_ * T_ * D_;
    size_t stride = (size_t)gridDim.x * blockDim.x;
    for (; i < total; i += stride) {
        __nv_bfloat16 hi, lo;
        split2(x[i], hi, lo);
        g_xh[i] = hi;
        g_xl[i] = lo;
    }
}

__global__ void init_kernel(const float* __restrict__ A) {
    int i = blockIdx.x * blockDim.x + threadIdx.x;
    if (i < N_ * H_) {
        const float4* a = reinterpret_cast<const float4*>(A + (size_t)i * 16);
        float4 a0 = a[0], a1 = a[1], a2 = a[2], a3 = a[3];
        float s = a0.x + a0.y + a0.z + a0.w + a1.x + a1.y + a1.z + a1.w
                + a2.x + a2.y + a2.z + a2.w + a3.x + a3.y + a3.z + a3.w;
        s *= (1.0f / 16.0f);
        g_h[0][i] = s;
        g_c[i] = s;
        __nv_bfloat16 hi, lo;
        split2(s, hi, lo);
        g_zh[0][i] = hi;
        g_zl[0][i] = lo;
    }
}

// ---- per-step attention (single pass, A rows in regs, 512 threads) ----
__global__ __launch_bounds__(512) void attn_kernel(const float* __restrict__ A, int cur) {
    int n = blockIdx.x;
    int tid = threadIdx.x;
    const float* __restrict__ hn = g_h[cur] + n * H_;
    const float* __restrict__ An = A + (size_t)n * H_ * 16;

    float4 ar[2][4];
    float s[16];
#pragma unroll
    for (int l = 0; l < 16; l++) s[l] = 0.0f;
#pragma unroll
    for (int r = 0; r < 2; r++) {
        int hh = tid + r * 512;
        float hv = hn[hh];
        const float4* ap = reinterpret_cast<const float4*>(An + hh * 16);
#pragma unroll
        for (int v = 0; v < 4; v++) {
            float4 a = ap[v];
            ar[r][v] = a;
            s[v * 4 + 0] += a.x * hv;
            s[v * 4 + 1] += a.y * hv;
            s[v * 4 + 2] += a.z * hv;
            s[v * 4 + 3] += a.w * hv;
        }
    }
#pragma unroll
    for (int off = 16; off > 0; off >>= 1)
#pragma unroll
        for (int l = 0; l < 16; l++) s[l] += __shfl_xor_sync(0xffffffffu, s[l], off);

    __shared__ float red[16][16];
    int wid = tid >> 5, lane = tid & 31;
    if (lane == 0)
#pragma unroll
        for (int l = 0; l < 16; l++) red[wid][l] = s[l];
    __syncthreads();

    float w[16];
    float mx = -1e30f;
#pragma unroll
    for (int l = 0; l < 16; l++) {
        float t = 0.0f;
#pragma unroll
        for (int ww = 0; ww < 16; ww++) t += red[ww][l];
        w[l] = t * 0.03125f;   // 1/sqrt(1024)
        mx = fmaxf(mx, w[l]);
    }
    float sum = 0.0f;
#pragma unroll
    for (int l = 0; l < 16; l++) { w[l] = expf(w[l] - mx); sum += w[l]; }
    float inv = 1.0f / sum;
#pragma unroll
    for (int l = 0; l < 16; l++) w[l] *= inv;

#pragma unroll
    for (int r = 0; r < 2; r++) {
        int hh = tid + r * 512;
        float acc = 0.0f;
#pragma unroll
        for (int v = 0; v < 4; v++) {
            float4 a = ar[r][v];
            acc += a.x * w[v * 4 + 0] + a.y * w[v * 4 + 1]
                 + a.z * w[v * 4 + 2] + a.w * w[v * 4 + 3];
        }
        __nv_bfloat16 hi, lo;
        split2(acc, hi, lo);
        g_ah[n * H_ + hh] = hi;
        g_al[n * H_ + hh] = lo;
    }
}

// ---- fused step: [h|attn|x_t] @ W (bf16-split mma.sync, cp.async 4-stage, ldmatrix) + LSTM ----
__global__ __launch_bounds__(256) void step_kernel(float* __restrict__ out, int t, int cur) {
    extern __shared__ __align__(16) unsigned char sm[];
    const unsigned int smb = (unsigned int)__cvta_generic_to_shared(sm);

    const int tid = threadIdx.x;
    const int bn = blockIdx.x * 128;   // gate-interleaved column base
    const int bm = blockIdx.y * 64;    // batch-row base
    const int nxt = cur ^ 1;

    const int wid = tid >> 5, lane = tid & 31;
    const int wm = wid >> 2, wn = wid & 3;        // 2 x 4 warp grid
    const int cprow = tid >> 2, cpq = tid & 3;    // cp.async mapping

    float acc[2][4][4];
#pragma unroll
    for (int mt = 0; mt < 2; mt++)
#pragma unroll
        for (int nt = 0; nt < 4; nt++)
#pragma unroll
            for (int q = 0; q < 4; q++) acc[mt][nt][q] = 0.0f;

    const __nv_bfloat16* zh = g_zh[cur];
    const __nv_bfloat16* zl = g_zl[cur];

    // ---- stage issue helper (inlined via lambda) ----
    auto issue = [&](int tl) {
        int k0 = tl * KC;
        unsigned int base = smb + (tl % STAGES) * STAGE_BYTES;
        // A tile: 64 rows x 32 halves (hi + lo)
        int n = bm + cprow;
        const __nv_bfloat16 *sh, *sl;
        if (k0 < H_) {
            sh = zh + n * H_ + k0;  sl = zl + n * H_ + k0;
        } else if (k0 < 2 * H_) {
            sh = g_ah + n * H_ + (k0 - H_);  sl = g_al + n * H_ + (k0 - H_);
        } else {
            size_t o = ((size_t)n * T_ + t) * D_ + (k0 - 2 * H_);
            sh = g_xh + o;  sl = g_xl + o;
        }
        cpa16(base + cprow * (SA * 2) + cpq * 16, sh + cpq * 8);
        cpa16(base + 64 * SA * 2 + cprow * (SA * 2) + cpq * 16, sl + cpq * 8);
        // B tile: 128 cols x 32 halves (hi + lo)
#pragma unroll
        for (int i = 0; i < 2; i++) {
            int cl = i * 64 + cprow;
            const __nv_bfloat16* wsrc_h = g_Wh + (size_t)(bn + cl) * KT_ + k0 + cpq * 8;
            const __nv_bfloat16* wsrc_l = g_Wl + (size_t)(bn + cl) * KT_ + k0 + cpq * 8;
            cpa16(base + 2 * 64 * SA * 2 + cl * (SB * 2) + cpq * 16, wsrc_h);
            cpa16(base + 2 * 64 * SA * 2 + 128 * SB * 2 + cl * (SB * 2) + cpq * 16, wsrc_l);
        }
    };

    // prologue: fill STAGES-1 stages
#pragma unroll
    for (int s = 0; s < STAGES - 1; s++) {
        issue(s);
        asm volatile("cp.async.commit_group;");
    }

    // ldmatrix per-lane address components (byte offsets within stage)
    const int a_row_l = (lane & 15);
    const int a_k_l = (lane >> 4) << 3;
    const int b_col_l = (lane & 7);
    const int b_k_l = (lane & 8) ? 8 : 0;

    for (int tile = 0; tile < NTILES; tile++) {
        asm volatile("cp.async.wait_group %0;" :: "n"(STAGES - 2));
        __syncthreads();
        int pf = tile + STAGES - 1;
        if (pf < NTILES) issue(pf);
        asm volatile("cp.async.commit_group;");

        unsigned int base = smb + (tile % STAGES) * STAGE_BYTES;
        unsigned int baseAh = base;
        unsigned int baseAl = base + 64 * SA * 2;
        unsigned int baseBh = base + 2 * 64 * SA * 2;
        unsigned int baseBl = baseBh + 128 * SB * 2;

#pragma unroll
        for (int kb = 0; kb < KC; kb += 16) {
            unsigned int ah[2][4], al[2][4], bh[4][2], bl[4][2];
#pragma unroll
            for (int mt = 0; mt < 2; mt++) {
                int row = wm * 32 + mt * 16 + a_row_l;
                int kk = kb + a_k_l;
                ldsm_x4(ah[mt], baseAh + (row * SA + kk) * 2);
                ldsm_x4(al[mt], baseAl + (row * SA + kk) * 2);
            }
#pragma unroll
            for (int nt = 0; nt < 4; nt++) {
                int col = wn * 32 + nt * 8 + b_col_l;
                int kk = kb + b_k_l;
                ldsm_x2(bh[nt], baseBh + (col * SB + kk) * 2);
                ldsm_x2(bl[nt], baseBl + (col * SB + kk) * 2);
            }
            // 3 passes, dependency reuse distance = 8
#pragma unroll
            for (int mt = 0; mt < 2; mt++)
#pragma unroll
                for (int nt = 0; nt < 4; nt++)
                    mma_bf16(acc[mt][nt], ah[mt], bh[nt]);
#pragma unroll
            for (int mt = 0; mt < 2; mt++)
#pragma unroll
                for (int nt = 0; nt < 4; nt++)
                    mma_bf16(acc[mt][nt], ah[mt], bl[nt]);
#pragma unroll
            for (int mt = 0; mt < 2; mt++)
#pragma unroll
                for (int nt = 0; nt < 4; nt++)
                    mma_bf16(acc[mt][nt], al[mt], bh[nt]);
        }
    }

    // ---- epilogue: regroup gates via smem, fused LSTM pointwise ----
    asm volatile("cp.async.wait_group 0;");
    __syncthreads();
    float* Cs = (float*)sm;
    const int g = lane >> 2, tg = lane & 3;
#pragma unroll
    for (int mt = 0; mt < 2; mt++)
#pragma unroll
        for (int nt = 0; nt < 4; nt++) {
            int r0 = wm * 32 + mt * 16 + g;
            int col = wn * 32 + nt * 8 + tg * 2;
            Cs[r0 * CS + col]           = acc[mt][nt][0];
            Cs[r0 * CS + col + 1]       = acc[mt][nt][1];
            Cs[(r0 + 8) * CS + col]     = acc[mt][nt][2];
            Cs[(r0 + 8) * CS + col + 1] = acc[mt][nt][3];
        }
    __syncthreads();

#pragma unroll
    for (int i = 0; i < 8; i++) {
        int lin = tid + i * 256;
        int m = lin >> 5, jj = lin & 31;
        float4 gg = *(const float4*)&Cs[m * CS + jj * 4];
        float4 bb = *(const float4*)&g_bv[bn + jj * 4];
        int n = bm + m;
        int j = (bn >> 2) + jj;
        float gi = gg.x + bb.x;
        float gf = gg.y + bb.y;
        float go = gg.z + bb.z;
        float gq = gg.w + bb.w;
        float cold = g_c[n * H_ + j];
        float cn = sigf(gf) * cold + sigf(gi) * tanhf(gq);
        float hn = sigf(go) * tanhf(cn);
        g_c[n * H_ + j] = cn;
        g_h[nxt][n * H_ + j] = hn;
        __nv_bfloat16 hi, lo;
        split2(hn, hi, lo);
        g_zh[nxt][n * H_ + j] = hi;
        g_zl[nxt][n * H_ + j] = lo;
        out[((size_t)n * T_ + t) * H_ + j] = hn;
    }
}

extern "C" void kernel_launch(void* const* d_in, const int* in_sizes, int n_in,
                              void* d_out, int out_size) {
    (void)in_sizes; (void)n_in; (void)out_size;
    const float* x     = (const float*)d_in[0];
    const float* A     = (const float*)d_in[1];
    const float* Wx    = (const float*)d_in[2];
    const float* Wh    = (const float*)d_in[3];
    const float* Wattn = (const float*)d_in[4];
    const float* b     = (const float*)d_in[5];
    float* out = (float*)d_out;

    cudaFuncSetAttribute(step_kernel, cudaFuncAttributeMaxDynamicSharedMemorySize,
                         STAGES * STAGE_BYTES);

    reorder_kernel<<<dim3(KT_ / 256, C4_), 256>>>(Wx, Wh, Wattn, b);
    xsplit_kernel<<<2048, 256>>>(x);
    init_kernel<<<(N_ * H_ + 255) / 256, 256>>>(A);

    int cur = 0;
    for (int t = 0; t < T_; t++) {
        attn_kernel<<<N_, 512>>>(A, cur);
        step_kernel<<<dim3(C4_ / 128, N_ / 64), 256, STAGES * STAGE_BYTES>>>(out, t, cur);
        cur ^= 1;
    }
}